// round 14
// baseline (speedup 1.0000x reference)
#include <cuda_runtime.h>
#include <math.h>

// ---------------------------------------------------------------------------
// QuantumNATExtendedQML — R13: conv1 mean computed ANALYTICALLY.
//   sum(conv1) = sum_k w_k * S_k + N*b, with S_k = T - edge sums + corners.
// conv1 accumulates only sumsq per channel + 9 image scalars (in the load
// phase); the per-element sum accumulation (6 FMA-pipe adds/row + shuffles)
// is deleted. conv2 prologue rebuilds mu1 from the scalars + w1/b1.
// Everything else identical to the 107.0us R12/R13 config.
// ---------------------------------------------------------------------------

#define NB 128

// persistent device scratch (no cudaMalloc allowed); zero-initialized.
__device__ double g_q1[8];                                 // sumsq per conv1 channel
__device__ double g_xs[9];                                 // T, R0, R223, C0, C223,
                                                           // x(0,0), x(0,223), x(223,0), x(223,223)
__device__ double g_stats2[8];                             // sum[4], sumsq[4] conv2 (true y)
__device__ unsigned int g_done;                            // pool-block counter
__device__ __align__(16) float g_h1[NB * 112 * 112 * 8];   // pooled extremum of s1*z, ch-last
__device__ __align__(16) float g_p2[NB * 56 * 56 * 4];     // pooled extremum of s2*y, ch-last
__device__ __align__(16) float g_feat[NB * 4];

__device__ __forceinline__ float warp_sum(float v) {
#pragma unroll
    for (int o = 16; o > 0; o >>= 1) v += __shfl_xor_sync(0xffffffffu, v, o);
    return v;
}

// ---------------------------------------------------------------------------
// Fused conv1: z' = s*conv(x) (s = sign(bn1g) folded into w,b) ->
// per-channel sumsq atomics + image scalars (for analytic mean) +
// 2x2 pooled max(z') (fp32, ch-last).
// grid(14, 128), block 224, 5 blocks/SM (regcap).
__global__ void __launch_bounds__(224, 5) k_conv1(const float* __restrict__ x,
                                                  const float* __restrict__ w,
                                                  const float* __restrict__ bias,
                                                  const float* __restrict__ bn1g) {
    __shared__ __align__(16) float tile[18][228];
    __shared__ double sacc[8];    // sumsq partials
    __shared__ double saccT[3];   // T, R0, R223 partials
    const int n = blockIdx.y, h0 = blockIdx.x * 16, tid = threadIdx.x;
    const int grp = tid & 3, k = tid >> 2, lane = tid & 31;

    if (tid < 8) sacc[tid] = 0.0;
    if (tid < 3) saccT[tid] = 0.0;

    // column-owner tile load + image-scalar accumulation (owned rows only)
    const float* xim = x + (size_t)n * 224 * 224;
    {
        float tloc = 0.f, r0loc = 0.f, r223loc = 0.f, c0loc = 0.f, c223loc = 0.f;
        for (int c = tid; c < 226; c += 224) {
            const int ww = c - 1;
            const bool cok = (ww >= 0) && (ww < 224);
#pragma unroll 2
            for (int r = 0; r < 18; r++) {
                int hh = h0 - 1 + r;
                float v = 0.f;
                if (cok && hh >= 0 && hh < 224) v = xim[hh * 224 + ww];
                tile[r][c] = v;
                if (r >= 1 && r <= 16) {      // owned rows (hh in [h0, h0+16))
                    tloc += v;
                    if (hh == 0) r0loc += v;
                    else if (hh == 223) r223loc += v;
                    if (ww == 0) c0loc += v;
                    else if (ww == 223) c223loc += v;
                    if ((hh == 0 || hh == 223) && (ww == 0 || ww == 223)) {
                        int ci = (hh == 223) * 2 + (ww == 223);
                        atomicAdd(&g_xs[5 + ci], (double)v);   // executes <=1/thread
                    }
                }
            }
        }
        float wt = warp_sum(tloc);
        float w0s = warp_sum(r0loc);
        float w1s = warp_sum(r223loc);
        if (lane == 0) {
            atomicAdd(&saccT[0], (double)wt);
            atomicAdd(&saccT[1], (double)w0s);
            atomicAdd(&saccT[2], (double)w1s);
        }
        if (tid == 1) atomicAdd(&g_xs[3], (double)c0loc);     // col 0 owner
        if (tid == 0) atomicAdd(&g_xs[4], (double)c223loc);   // col 223 owner (2nd pass)
    }

    float wr[18], br[2];
#pragma unroll
    for (int j = 0; j < 2; j++) {
        int oc = grp * 2 + j;
        float s = (bn1g[oc] >= 0.f) ? 1.f : -1.f;
#pragma unroll
        for (int t = 0; t < 9; t++) wr[j * 9 + t] = w[oc * 9 + t] * s;
        br[j] = bias[oc] * s;
    }
    __syncthreads();

    const int c0 = 4 * k;
    float w0[6], w1[6];
    {
        float4 a0 = *(const float4*)&tile[0][c0];
        float2 b0 = *(const float2*)&tile[0][c0 + 4];
        w0[0] = a0.x; w0[1] = a0.y; w0[2] = a0.z; w0[3] = a0.w; w0[4] = b0.x; w0[5] = b0.y;
        float4 a1 = *(const float4*)&tile[1][c0];
        float2 b1 = *(const float2*)&tile[1][c0 + 4];
        w1[0] = a1.x; w1[1] = a1.y; w1[2] = a1.z; w1[3] = a1.w; w1[4] = b1.x; w1[5] = b1.y;
    }

    float q[2] = {0.f, 0.f};
    float mx[2][2];
    float* psel = &g_h1[(((size_t)n * 112 + blockIdx.x * 8) * 112 + 2 * k) * 8 + 2 * grp];

#pragma unroll 4
    for (int r = 0; r < 16; r++) {
        float w2v[6];
        {
            float4 a = *(const float4*)&tile[r + 2][c0];
            float2 b = *(const float2*)&tile[r + 2][c0 + 4];
            w2v[0] = a.x; w2v[1] = a.y; w2v[2] = a.z; w2v[3] = a.w; w2v[4] = b.x; w2v[5] = b.y;
        }
#pragma unroll
        for (int j = 0; j < 2; j++) {
            float z[4];
#pragma unroll
            for (int p = 0; p < 4; p++) {
                float zz = br[j];
                zz = fmaf(wr[j * 9 + 0], w0[p + 0], zz);
                zz = fmaf(wr[j * 9 + 1], w0[p + 1], zz);
                zz = fmaf(wr[j * 9 + 2], w0[p + 2], zz);
                zz = fmaf(wr[j * 9 + 3], w1[p + 0], zz);
                zz = fmaf(wr[j * 9 + 4], w1[p + 1], zz);
                zz = fmaf(wr[j * 9 + 5], w1[p + 2], zz);
                zz = fmaf(wr[j * 9 + 6], w2v[p + 0], zz);
                zz = fmaf(wr[j * 9 + 7], w2v[p + 1], zz);
                zz = fmaf(wr[j * 9 + 8], w2v[p + 2], zz);
                z[p] = zz;
            }
            q[j] = fmaf(z[0], z[0], fmaf(z[1], z[1], fmaf(z[2], z[2], fmaf(z[3], z[3], q[j]))));
            float h0m = fmaxf(z[0], z[1]), h1m = fmaxf(z[2], z[3]);
            if (r & 1) {
                mx[j][0] = fmaxf(mx[j][0], h0m);
                mx[j][1] = fmaxf(mx[j][1], h1m);
            } else {
                mx[j][0] = h0m;
                mx[j][1] = h1m;
            }
        }
        if (r & 1) {
            *(float2*)psel       = make_float2(mx[0][0], mx[1][0]);
            *(float2*)(psel + 8) = make_float2(mx[0][1], mx[1][1]);
            psel += 112 * 8;
        }
#pragma unroll
        for (int i = 0; i < 6; i++) { w0[i] = w1[i]; w1[i] = w2v[i]; }
    }

    // same-group reduction of sumsq (lanes 4 apart); sumsq is sign-invariant.
#pragma unroll
    for (int j = 0; j < 2; j++) {
        float qq = q[j];
#pragma unroll
        for (int o = 4; o < 32; o <<= 1) qq += __shfl_xor_sync(0xffffffffu, qq, o);
        if (lane < 4) atomicAdd(&sacc[lane * 2 + j], (double)qq);
    }
    __syncthreads();
    if (tid < 8) atomicAdd(&g_q1[tid], sacc[tid]);
    else if (tid < 11) atomicAdd(&g_xs[tid - 8], saccT[tid - 8]);
}

// ---------------------------------------------------------------------------
// conv2 (oc 0..3): prologue derives bn1 affine: mu1 analytically from g_xs +
// w1/b1; var from g_q1. Tile load: h = relu(|a1|*stored + c1). s2 folded into
// w2,b2; stats re-signed to g_stats2; in-block 2x2 pooled max(y') out.
// grid(14, 128), block 224.
__global__ void __launch_bounds__(224) k_conv2(const float* __restrict__ w2,
                                               const float* __restrict__ b2,
                                               const float* __restrict__ w1,
                                               const float* __restrict__ b1,
                                               const float* __restrict__ bn1g,
                                               const float* __restrict__ bn1b,
                                               const float* __restrict__ bn2g) {
    __shared__ float tile[8][10][120];
    __shared__ float4 wq[72];
    __shared__ float4 ybuf[8][112];
    __shared__ float bsh[4], s_s2[4], s_a1[8], s_c1[8];
    __shared__ double sacc[8];
    const int n = blockIdx.y, h0 = blockIdx.x * 8, tid = threadIdx.x;

    if (tid < 8) {
        const double N = 128.0 * 224.0 * 224.0;
        double T = g_xs[0], R0 = g_xs[1], R223 = g_xs[2], C0 = g_xs[3], C223 = g_xs[4];
        double x00 = g_xs[5], x0W = g_xs[6], xH0 = g_xs[7], xHW = g_xs[8];
        double Ssum = 0.0;
#pragma unroll
        for (int kh = 0; kh < 3; kh++)
#pragma unroll
            for (int kw = 0; kw < 3; kw++) {
                double S = T;
                if (kh == 2) S -= R0;
                if (kh == 0) S -= R223;
                if (kw == 2) S -= C0;
                if (kw == 0) S -= C223;
                if (kh == 2 && kw == 2) S += x00;
                if (kh == 2 && kw == 0) S += x0W;
                if (kh == 0 && kw == 2) S += xH0;
                if (kh == 0 && kw == 0) S += xHW;
                Ssum += (double)w1[tid * 9 + kh * 3 + kw] * S;
            }
        double mu = Ssum / N + (double)b1[tid];
        double var = g_q1[tid] / N - mu * mu;
        double a = (double)bn1g[tid] * rsqrt(var + 1e-5);
        s_a1[tid] = fabsf((float)a);
        s_c1[tid] = (float)((double)bn1b[tid] - mu * a);
    }
    if (tid < 72) {
        float sg0 = bn2g[0] >= 0.f ? 1.f : -1.f;
        float sg1 = bn2g[1] >= 0.f ? 1.f : -1.f;
        float sg2 = bn2g[2] >= 0.f ? 1.f : -1.f;
        float sg3 = bn2g[3] >= 0.f ? 1.f : -1.f;
        wq[tid] = make_float4(w2[tid] * sg0, w2[72 + tid] * sg1,
                              w2[144 + tid] * sg2, w2[216 + tid] * sg3);
    }
    if (tid < 4) {
        float sgn = bn2g[tid] >= 0.f ? 1.f : -1.f;
        s_s2[tid] = sgn;
        bsh[tid] = b2[tid] * sgn;
    }
    if (tid < 8) sacc[tid] = 0.0;
    __syncthreads();

    float a1r[8], c1r[8];
#pragma unroll
    for (int ch = 0; ch < 8; ch++) { a1r[ch] = s_a1[ch]; c1r[ch] = s_c1[ch]; }

    // column-owner tile load: thread owns tile col c (<114), loops 10 rows
    for (int c = tid; c < 114; c += 224) {
        const int ww = c - 1;
        const bool cok = (ww >= 0) && (ww < 112);
#pragma unroll 2
        for (int r = 0; r < 10; r++) {
            int hh = h0 - 1 + r;
            float v[8];
            if (cok && hh >= 0 && hh < 112) {
                size_t base = (((size_t)n * 112 + hh) * 112 + ww) * 8;
                float4 x0 = *(const float4*)&g_h1[base];
                float4 x1 = *(const float4*)&g_h1[base + 4];
                float raw[8] = {x0.x, x0.y, x0.z, x0.w, x1.x, x1.y, x1.z, x1.w};
#pragma unroll
                for (int ch = 0; ch < 8; ch++)
                    v[ch] = fmaxf(fmaf(raw[ch], a1r[ch], c1r[ch]), 0.f);
            } else {
#pragma unroll
                for (int ch = 0; ch < 8; ch++) v[ch] = 0.f;
            }
#pragma unroll
            for (int ch = 0; ch < 8; ch++) tile[ch][r][c] = v[ch];
        }
    }
    __syncthreads();

    const int r = tid / 28, g = tid % 28;
    float y[4][4];
    {
        float b0 = bsh[0], b1v = bsh[1], b2v = bsh[2], b3 = bsh[3];
#pragma unroll
        for (int p = 0; p < 4; p++) {
            y[0][p] = b0; y[1][p] = b1v; y[2][p] = b2v; y[3][p] = b3;
        }
    }

#pragma unroll 1
    for (int ic = 0; ic < 8; ic++) {
#pragma unroll
        for (int kh = 0; kh < 3; kh++) {
            const float4 va = *(const float4*)&tile[ic][r + kh][4 * g];
            const float2 vb = *(const float2*)&tile[ic][r + kh][4 * g + 4];
            float t[6] = {va.x, va.y, va.z, va.w, vb.x, vb.y};
#pragma unroll
            for (int kw = 0; kw < 3; kw++) {
                float4 wv = wq[ic * 9 + kh * 3 + kw];
#pragma unroll
                for (int p = 0; p < 4; p++) {
                    float u = t[p + kw];
                    y[0][p] = fmaf(wv.x, u, y[0][p]);
                    y[1][p] = fmaf(wv.y, u, y[1][p]);
                    y[2][p] = fmaf(wv.z, u, y[2][p]);
                    y[3][p] = fmaf(wv.w, u, y[3][p]);
                }
            }
        }
    }

    // bn2 stats on true y (sum re-signed; sumsq sign-invariant)
#pragma unroll
    for (int j = 0; j < 4; j++) {
        float s = (y[j][0] + y[j][1]) + (y[j][2] + y[j][3]);
        float qq = fmaf(y[j][0], y[j][0], fmaf(y[j][1], y[j][1],
                   fmaf(y[j][2], y[j][2], y[j][3] * y[j][3])));
        float ws = warp_sum(s);
        float wq = warp_sum(qq);
        if ((tid & 31) == 0) {
            atomicAdd(&sacc[j], (double)(ws * s_s2[j]));
            atomicAdd(&sacc[4 + j], (double)wq);
        }
    }

    // stash y' into ybuf for in-block 2x2 max pooling
#pragma unroll
    for (int p = 0; p < 4; p++)
        ybuf[r][4 * g + p] = make_float4(y[0][p], y[1][p], y[2][p], y[3][p]);
    __syncthreads();

    // 224 threads = 4 pooled rows x 56 pooled cols, single plane out
    {
        const int ppr = tid / 56, ppw = tid % 56;
        float4 u0 = ybuf[2 * ppr][2 * ppw];
        float4 u1 = ybuf[2 * ppr][2 * ppw + 1];
        float4 u2 = ybuf[2 * ppr + 1][2 * ppw];
        float4 u3 = ybuf[2 * ppr + 1][2 * ppw + 1];
        float4 mx;
        mx.x = fmaxf(fmaxf(u0.x, u1.x), fmaxf(u2.x, u3.x));
        mx.y = fmaxf(fmaxf(u0.y, u1.y), fmaxf(u2.y, u3.y));
        mx.z = fmaxf(fmaxf(u0.z, u1.z), fmaxf(u2.z, u3.z));
        mx.w = fmaxf(fmaxf(u0.w, u1.w), fmaxf(u2.w, u3.w));
        size_t o = (((size_t)n * 56 + (blockIdx.x * 4 + ppr)) * 56 + ppw) * 4;
        *(float4*)&g_p2[o] = mx;
    }
    if (tid < 8) atomicAdd(&g_stats2[tid], sacc[tid]);
}

// ---------------------------------------------------------------------------
// Quantum circuit helpers.
template <int Q>
__device__ __forceinline__ void ry_gate(float2* st, float t) {
    float s, c;
    sincosf(0.5f * t, &s, &c);
    const int m = 8 >> Q;
#pragma unroll
    for (int i = 0; i < 16; i++)
        if (!(i & m)) {
            float2 a0 = st[i], a1 = st[i | m];
            st[i]     = make_float2(c * a0.x - s * a1.x, c * a0.y - s * a1.y);
            st[i | m] = make_float2(s * a0.x + c * a1.x, s * a0.y + c * a1.y);
        }
}
template <int Q>
__device__ __forceinline__ void rz_gate(float2* st, float t) {
    float s, c;
    sincosf(0.5f * t, &s, &c);
    const int m = 8 >> Q;
#pragma unroll
    for (int i = 0; i < 16; i++)
        if (!(i & m)) {
            float2 a0 = st[i], a1 = st[i | m];
            st[i]     = make_float2(c * a0.x + s * a0.y, c * a0.y - s * a0.x);
            st[i | m] = make_float2(c * a1.x - s * a1.y, c * a1.y + s * a1.x);
        }
}
template <int Q>
__device__ __forceinline__ void rx_gate(float2* st, float t) {
    float s, c;
    sincosf(0.5f * t, &s, &c);
    const int m = 8 >> Q;
#pragma unroll
    for (int i = 0; i < 16; i++)
        if (!(i & m)) {
            float2 a0 = st[i], a1 = st[i | m];
            st[i]     = make_float2(c * a0.x + s * a1.y, c * a0.y - s * a1.x);
            st[i | m] = make_float2(c * a1.x + s * a0.y, c * a1.y - s * a0.x);
        }
}
template <int C, int T>
__device__ __forceinline__ void cnot_gate(float2* st) {
    const int mc = 8 >> C, mt = 8 >> T;
#pragma unroll
    for (int i = 0; i < 16; i++)
        if ((i & mc) && !(i & mt)) {
            float2 tmp = st[i];
            st[i] = st[i | mt];
            st[i | mt] = tmp;
        }
}

// ---------------------------------------------------------------------------
// pool_mean + fused final.  grid(128), block 256.
__global__ void k_pool_final(const float* __restrict__ bn2g,
                             const float* __restrict__ bn2b,
                             const float* __restrict__ theta,
                             const float* __restrict__ rho,
                             const float* __restrict__ ng,
                             const float* __restrict__ nb,
                             float* __restrict__ out) {
    __shared__ float s_a2[4], s_c2[4];
    __shared__ unsigned int s_last;
    const int n = blockIdx.x, tid = threadIdx.x;
    if (tid < 4) {
        double N = 128.0 * 112.0 * 112.0;
        double mu = g_stats2[tid] / N;
        double var = g_stats2[4 + tid] / N - mu * mu;
        double a = (double)bn2g[tid] * rsqrt(var + 1e-5);
        s_a2[tid] = fabsf((float)a);
        s_c2[tid] = (float)((double)bn2b[tid] - mu * a);
    }
    __syncthreads();
    const float4 av = *(const float4*)s_a2;
    const float4 cv = *(const float4*)s_c2;
    const float4* psel = (const float4*)&g_p2[(size_t)n * 56 * 56 * 4];
    float4 acc = make_float4(0.f, 0.f, 0.f, 0.f);

    for (int p = tid; p < 56 * 56; p += 256) {
        float4 mx = psel[p];
        acc.x += fmaxf(fmaf(mx.x, av.x, cv.x), 0.f);
        acc.y += fmaxf(fmaf(mx.y, av.y, cv.y), 0.f);
        acc.z += fmaxf(fmaf(mx.z, av.z, cv.z), 0.f);
        acc.w += fmaxf(fmaf(mx.w, av.w, cv.w), 0.f);
    }
    __shared__ float4 sm[8];
    acc.x = warp_sum(acc.x); acc.y = warp_sum(acc.y);
    acc.z = warp_sum(acc.z); acc.w = warp_sum(acc.w);
    if ((tid & 31) == 0) sm[tid >> 5] = acc;
    __syncthreads();
    if (tid == 0) {
        float4 t = make_float4(0.f, 0.f, 0.f, 0.f);
#pragma unroll
        for (int i = 0; i < 8; i++) {
            t.x += sm[i].x; t.y += sm[i].y; t.z += sm[i].z; t.w += sm[i].w;
        }
        *(float4*)&g_feat[n * 4] =
            make_float4(t.x / 3136.f, t.y / 3136.f, t.z / 3136.f, t.w / 3136.f);
        __threadfence();
        s_last = atomicAdd(&g_done, 1u);
    }
    __syncthreads();
    if (s_last != NB - 1) return;
    __threadfence();

    if (tid == 0) g_done = 0;
    if (tid < 8)  g_q1[tid] = 0.0;
    if (tid < 9)  g_xs[tid] = 0.0;
    if (tid < 8)  g_stats2[tid] = 0.0;
    if (tid >= 128) return;

    float f[4];
#pragma unroll
    for (int j = 0; j < 4; j++) f[j] = g_feat[tid * 4 + j];

    __shared__ double ssum, ssq;
    if (tid == 0) { ssum = 0.0; ssq = 0.0; }
    __syncthreads();
    float lf = f[0] + f[1] + f[2] + f[3];
    float lq = f[0] * f[0] + f[1] * f[1] + f[2] * f[2] + f[3] * f[3];
    float ws = warp_sum(lf), wq = warp_sum(lq);
    if ((tid & 31) == 0) { atomicAdd(&ssum, (double)ws); atomicAdd(&ssq, (double)wq); }
    __syncthreads();
    double mean = ssum / 512.0;
    double var1 = (ssq - 512.0 * mean * mean) / 511.0;
    if (var1 < 0.0) var1 = 0.0;
    float scale = (float)(3.14159265358979323846 / (sqrt(var1) + 1e-6));
    float sc[4];
#pragma unroll
    for (int j = 0; j < 4; j++) sc[j] = (float)((double)f[j] - mean) * scale;

    float2 st[16];
#pragma unroll
    for (int i = 0; i < 16; i++) st[i] = make_float2(0.f, 0.f);
    st[0].x = 1.f;

    ry_gate<0>(st, sc[0]); ry_gate<1>(st, sc[1]); ry_gate<2>(st, sc[2]); ry_gate<3>(st, sc[3]);

    ry_gate<0>(st, theta[0]);  rz_gate<0>(st, theta[1]);  rx_gate<0>(st, theta[2]);
    ry_gate<1>(st, theta[3]);  rz_gate<1>(st, theta[4]);  rx_gate<1>(st, theta[5]);
    ry_gate<2>(st, theta[6]);  rz_gate<2>(st, theta[7]);  rx_gate<2>(st, theta[8]);
    ry_gate<3>(st, theta[9]);  rz_gate<3>(st, theta[10]); rx_gate<3>(st, theta[11]);

    cnot_gate<0, 1>(st); cnot_gate<1, 2>(st); cnot_gate<2, 3>(st);

    ry_gate<0>(st, rho[0]);  rz_gate<0>(st, rho[1]);  rx_gate<0>(st, rho[2]);
    ry_gate<1>(st, rho[3]);  rz_gate<1>(st, rho[4]);  rx_gate<1>(st, rho[5]);
    ry_gate<2>(st, rho[6]);  rz_gate<2>(st, rho[7]);  rx_gate<2>(st, rho[8]);
    ry_gate<3>(st, rho[9]);  rz_gate<3>(st, rho[10]); rx_gate<3>(st, rho[11]);

    cnot_gate<1, 0>(st); cnot_gate<2, 1>(st); cnot_gate<3, 2>(st);

    float pr[16];
#pragma unroll
    for (int i = 0; i < 16; i++) pr[i] = st[i].x * st[i].x + st[i].y * st[i].y;

    float e[4];
#pragma unroll
    for (int q = 0; q < 4; q++) {
        const int m = 8 >> q;
        float a = 0.f;
#pragma unroll
        for (int i = 0; i < 16; i++) a += (i & m) ? -pr[i] : pr[i];
        e[q] = a;
    }

    __shared__ double s1, s2;
#pragma unroll
    for (int j = 0; j < 4; j++) {
        if (tid == 0) { s1 = 0.0; s2 = 0.0; }
        __syncthreads();
        float v = e[j];
        float w1 = warp_sum(v), w2 = warp_sum(v * v);
        if ((tid & 31) == 0) { atomicAdd(&s1, (double)w1); atomicAdd(&s2, (double)w2); }
        __syncthreads();
        double mu = s1 / 128.0;
        double vv = s2 / 128.0 - mu * mu;
        out[tid * 4 + j] =
            (float)(((double)v - mu) * rsqrt(vv + 1e-5) * (double)ng[j] + (double)nb[j]);
        __syncthreads();
    }
}

// ---------------------------------------------------------------------------
extern "C" void kernel_launch(void* const* d_in, const int* in_sizes, int n_in,
                              void* d_out, int out_size) {
    const float* x     = (const float*)d_in[0];
    const float* w1    = (const float*)d_in[1];
    const float* b1    = (const float*)d_in[2];
    const float* bn1g  = (const float*)d_in[3];
    const float* bn1b  = (const float*)d_in[4];
    const float* w2    = (const float*)d_in[5];
    const float* b2    = (const float*)d_in[6];
    const float* bn2g  = (const float*)d_in[7];
    const float* bn2b  = (const float*)d_in[8];
    const float* theta = (const float*)d_in[9];
    const float* rho   = (const float*)d_in[10];
    const float* ng    = (const float*)d_in[11];
    const float* nbp   = (const float*)d_in[12];
    float* out = (float*)d_out;

    k_conv1<<<dim3(14, NB), 224>>>(x, w1, b1, bn1g);
    k_conv2<<<dim3(14, NB), 224>>>(w2, b2, w1, b1, bn1g, bn1b, bn2g);
    k_pool_final<<<NB, 256>>>(bn2g, bn2b, theta, rho, ng, nbp, out);
}

// round 15
// speedup vs baseline: 1.1523x; 1.1523x over previous
#include <cuda_runtime.h>
#include <math.h>

// ---------------------------------------------------------------------------
// QuantumNATExtendedQML — R14: analytic conv1 mean, done right.
// R12 structure (107.0us best: regcap(224,5), unroll 4) + conv-core sum
// accumulation deleted. Image scalars gathered at ZERO hot-loop cost:
//   T: unconditional FADD during tile load (halo loads are 0).
//   edges/corners: tiny post-sync smem epilogue, predicated per block.
// conv2 prologue rebuilds mu1 analytically (algebra proven in R13).
// Pipeline: conv1 -> conv2 -> pool_final (3 launches).
// ---------------------------------------------------------------------------

#define NB 128

// persistent device scratch (no cudaMalloc allowed); zero-initialized.
__device__ double g_q1[8];                                 // sumsq per conv1 channel
__device__ double g_xs[9];                                 // T, R0, R223, C0, C223,
                                                           // x(0,0), x(0,223), x(223,0), x(223,223)
__device__ double g_stats2[8];                             // sum[4], sumsq[4] conv2 (true y)
__device__ unsigned int g_done;                            // pool-block counter
__device__ __align__(16) float g_h1[NB * 112 * 112 * 8];   // pooled extremum of s1*z, ch-last
__device__ __align__(16) float g_p2[NB * 56 * 56 * 4];     // pooled extremum of s2*y, ch-last
__device__ __align__(16) float g_feat[NB * 4];

__device__ __forceinline__ float warp_sum(float v) {
#pragma unroll
    for (int o = 16; o > 0; o >>= 1) v += __shfl_xor_sync(0xffffffffu, v, o);
    return v;
}

// ---------------------------------------------------------------------------
// Fused conv1: z' = s*conv(x) -> per-channel sumsq atomics + image scalars
// (analytic mean) + 2x2 pooled max(z') (fp32, ch-last).
// grid(14, 128), block 224, 5 blocks/SM (regcap).
__global__ void __launch_bounds__(224, 5) k_conv1(const float* __restrict__ x,
                                                  const float* __restrict__ w,
                                                  const float* __restrict__ bias,
                                                  const float* __restrict__ bn1g) {
    __shared__ __align__(16) float tile[18][228];
    __shared__ double sacc[9];    // [0..7] sumsq partials, [8] T partial
    const int n = blockIdx.y, h0 = blockIdx.x * 16, tid = threadIdx.x;
    const int grp = tid & 3, k = tid >> 2, lane = tid & 31;

    if (tid < 9) sacc[tid] = 0.0;

    // column-owner tile load; T accumulated unconditionally (halo = 0)
    const float* xim = x + (size_t)n * 224 * 224;
    float tloc = 0.f;
    for (int c = tid; c < 226; c += 224) {
        const int ww = c - 1;
        const bool cok = (ww >= 0) && (ww < 224);
#pragma unroll 2
        for (int r = 0; r < 18; r++) {
            int hh = h0 - 1 + r;
            float v = 0.f;
            if (cok && hh >= 0 && hh < 224) v = xim[hh * 224 + ww];
            tile[r][c] = v;
            if (r >= 1 && r <= 16) tloc += v;   // compile-time condition
        }
    }

    float wr[18], br[2];
#pragma unroll
    for (int j = 0; j < 2; j++) {
        int oc = grp * 2 + j;
        float s = (bn1g[oc] >= 0.f) ? 1.f : -1.f;
#pragma unroll
        for (int t = 0; t < 9; t++) wr[j * 9 + t] = w[oc * 9 + t] * s;
        br[j] = bias[oc] * s;
    }
    __syncthreads();

    // ---- scalar epilogue (once per block, outside hot loops) ----
    {
        float wt = warp_sum(tloc);
        if (lane == 0) atomicAdd(&sacc[8], (double)wt);
        if (blockIdx.x == 0) {       // rows with hh==0 live at tile r=1
            float r0 = tile[1][tid] + ((tid + 224 < 226) ? tile[1][tid + 224] : 0.f);
            float wr0 = warp_sum(r0);
            if (lane == 0) atomicAdd(&g_xs[1], (double)wr0);
        }
        if (blockIdx.x == 13) {      // rows with hh==223 live at tile r=16
            float r1 = tile[16][tid] + ((tid + 224 < 226) ? tile[16][tid + 224] : 0.f);
            float wr1 = warp_sum(r1);
            if (lane == 0) atomicAdd(&g_xs[2], (double)wr1);
        }
        if (tid == 0) {
            float c0 = 0.f, c1 = 0.f;
#pragma unroll
            for (int r = 1; r <= 16; r++) { c0 += tile[r][1]; c1 += tile[r][224]; }
            atomicAdd(&g_xs[3], (double)c0);
            atomicAdd(&g_xs[4], (double)c1);
            if (blockIdx.x == 0) {
                atomicAdd(&g_xs[5], (double)tile[1][1]);
                atomicAdd(&g_xs[6], (double)tile[1][224]);
            }
            if (blockIdx.x == 13) {
                atomicAdd(&g_xs[7], (double)tile[16][1]);
                atomicAdd(&g_xs[8], (double)tile[16][224]);
            }
        }
    }

    const int c0 = 4 * k;
    float w0[6], w1[6];
    {
        float4 a0 = *(const float4*)&tile[0][c0];
        float2 b0 = *(const float2*)&tile[0][c0 + 4];
        w0[0] = a0.x; w0[1] = a0.y; w0[2] = a0.z; w0[3] = a0.w; w0[4] = b0.x; w0[5] = b0.y;
        float4 a1 = *(const float4*)&tile[1][c0];
        float2 b1 = *(const float2*)&tile[1][c0 + 4];
        w1[0] = a1.x; w1[1] = a1.y; w1[2] = a1.z; w1[3] = a1.w; w1[4] = b1.x; w1[5] = b1.y;
    }

    float q[2] = {0.f, 0.f};
    float mx[2][2];
    float* psel = &g_h1[(((size_t)n * 112 + blockIdx.x * 8) * 112 + 2 * k) * 8 + 2 * grp];

#pragma unroll 4
    for (int r = 0; r < 16; r++) {
        float w2v[6];
        {
            float4 a = *(const float4*)&tile[r + 2][c0];
            float2 b = *(const float2*)&tile[r + 2][c0 + 4];
            w2v[0] = a.x; w2v[1] = a.y; w2v[2] = a.z; w2v[3] = a.w; w2v[4] = b.x; w2v[5] = b.y;
        }
#pragma unroll
        for (int j = 0; j < 2; j++) {
            float z[4];
#pragma unroll
            for (int p = 0; p < 4; p++) {
                float zz = br[j];
                zz = fmaf(wr[j * 9 + 0], w0[p + 0], zz);
                zz = fmaf(wr[j * 9 + 1], w0[p + 1], zz);
                zz = fmaf(wr[j * 9 + 2], w0[p + 2], zz);
                zz = fmaf(wr[j * 9 + 3], w1[p + 0], zz);
                zz = fmaf(wr[j * 9 + 4], w1[p + 1], zz);
                zz = fmaf(wr[j * 9 + 5], w1[p + 2], zz);
                zz = fmaf(wr[j * 9 + 6], w2v[p + 0], zz);
                zz = fmaf(wr[j * 9 + 7], w2v[p + 1], zz);
                zz = fmaf(wr[j * 9 + 8], w2v[p + 2], zz);
                z[p] = zz;
            }
            q[j] = fmaf(z[0], z[0], fmaf(z[1], z[1], fmaf(z[2], z[2], fmaf(z[3], z[3], q[j]))));
            float h0m = fmaxf(z[0], z[1]), h1m = fmaxf(z[2], z[3]);
            if (r & 1) {
                mx[j][0] = fmaxf(mx[j][0], h0m);
                mx[j][1] = fmaxf(mx[j][1], h1m);
            } else {
                mx[j][0] = h0m;
                mx[j][1] = h1m;
            }
        }
        if (r & 1) {
            *(float2*)psel       = make_float2(mx[0][0], mx[1][0]);
            *(float2*)(psel + 8) = make_float2(mx[0][1], mx[1][1]);
            psel += 112 * 8;
        }
#pragma unroll
        for (int i = 0; i < 6; i++) { w0[i] = w1[i]; w1[i] = w2v[i]; }
    }

    // same-group sumsq reduction (lanes 4 apart); sumsq is sign-invariant.
#pragma unroll
    for (int j = 0; j < 2; j++) {
        float qq = q[j];
#pragma unroll
        for (int o = 4; o < 32; o <<= 1) qq += __shfl_xor_sync(0xffffffffu, qq, o);
        if (lane < 4) atomicAdd(&sacc[lane * 2 + j], (double)qq);
    }
    __syncthreads();
    if (tid < 8) atomicAdd(&g_q1[tid], sacc[tid]);
    else if (tid == 8) atomicAdd(&g_xs[0], sacc[8]);
}

// ---------------------------------------------------------------------------
// conv2 (oc 0..3): prologue derives bn1 affine — mu1 analytically from g_xs +
// w1/b1 (algebra proven in R13); var from g_q1. Rest identical to R12.
// grid(14, 128), block 224.
__global__ void __launch_bounds__(224) k_conv2(const float* __restrict__ w2,
                                               const float* __restrict__ b2,
                                               const float* __restrict__ w1,
                                               const float* __restrict__ b1,
                                               const float* __restrict__ bn1g,
                                               const float* __restrict__ bn1b,
                                               const float* __restrict__ bn2g) {
    __shared__ float tile[8][10][120];
    __shared__ float4 wq[72];
    __shared__ float4 ybuf[8][112];
    __shared__ float bsh[4], s_s2[4], s_a1[8], s_c1[8];
    __shared__ double sacc[8];
    const int n = blockIdx.y, h0 = blockIdx.x * 8, tid = threadIdx.x;

    if (tid < 8) {
        const double N = 128.0 * 224.0 * 224.0;
        double T = g_xs[0], R0 = g_xs[1], R223 = g_xs[2], C0 = g_xs[3], C223 = g_xs[4];
        double x00 = g_xs[5], x0W = g_xs[6], xH0 = g_xs[7], xHW = g_xs[8];
        double Ssum = 0.0;
#pragma unroll
        for (int kh = 0; kh < 3; kh++)
#pragma unroll
            for (int kw = 0; kw < 3; kw++) {
                double S = T;
                if (kh == 2) S -= R0;
                if (kh == 0) S -= R223;
                if (kw == 2) S -= C0;
                if (kw == 0) S -= C223;
                if (kh == 2 && kw == 2) S += x00;
                if (kh == 2 && kw == 0) S += x0W;
                if (kh == 0 && kw == 2) S += xH0;
                if (kh == 0 && kw == 0) S += xHW;
                Ssum += (double)w1[tid * 9 + kh * 3 + kw] * S;
            }
        double mu = Ssum / N + (double)b1[tid];
        double var = g_q1[tid] / N - mu * mu;
        double a = (double)bn1g[tid] * rsqrt(var + 1e-5);
        s_a1[tid] = fabsf((float)a);
        s_c1[tid] = (float)((double)bn1b[tid] - mu * a);
    }
    if (tid < 72) {
        float sg0 = bn2g[0] >= 0.f ? 1.f : -1.f;
        float sg1 = bn2g[1] >= 0.f ? 1.f : -1.f;
        float sg2 = bn2g[2] >= 0.f ? 1.f : -1.f;
        float sg3 = bn2g[3] >= 0.f ? 1.f : -1.f;
        wq[tid] = make_float4(w2[tid] * sg0, w2[72 + tid] * sg1,
                              w2[144 + tid] * sg2, w2[216 + tid] * sg3);
    }
    if (tid < 4) {
        float sgn = bn2g[tid] >= 0.f ? 1.f : -1.f;
        s_s2[tid] = sgn;
        bsh[tid] = b2[tid] * sgn;
    }
    if (tid < 8) sacc[tid] = 0.0;
    __syncthreads();

    float a1r[8], c1r[8];
#pragma unroll
    for (int ch = 0; ch < 8; ch++) { a1r[ch] = s_a1[ch]; c1r[ch] = s_c1[ch]; }

    // column-owner tile load: thread owns tile col c (<114), loops 10 rows
    for (int c = tid; c < 114; c += 224) {
        const int ww = c - 1;
        const bool cok = (ww >= 0) && (ww < 112);
#pragma unroll 2
        for (int r = 0; r < 10; r++) {
            int hh = h0 - 1 + r;
            float v[8];
            if (cok && hh >= 0 && hh < 112) {
                size_t base = (((size_t)n * 112 + hh) * 112 + ww) * 8;
                float4 x0 = *(const float4*)&g_h1[base];
                float4 x1 = *(const float4*)&g_h1[base + 4];
                float raw[8] = {x0.x, x0.y, x0.z, x0.w, x1.x, x1.y, x1.z, x1.w};
#pragma unroll
                for (int ch = 0; ch < 8; ch++)
                    v[ch] = fmaxf(fmaf(raw[ch], a1r[ch], c1r[ch]), 0.f);
            } else {
#pragma unroll
                for (int ch = 0; ch < 8; ch++) v[ch] = 0.f;
            }
#pragma unroll
            for (int ch = 0; ch < 8; ch++) tile[ch][r][c] = v[ch];
        }
    }
    __syncthreads();

    const int r = tid / 28, g = tid % 28;
    float y[4][4];
    {
        float b0 = bsh[0], b1v = bsh[1], b2v = bsh[2], b3 = bsh[3];
#pragma unroll
        for (int p = 0; p < 4; p++) {
            y[0][p] = b0; y[1][p] = b1v; y[2][p] = b2v; y[3][p] = b3;
        }
    }

#pragma unroll 1
    for (int ic = 0; ic < 8; ic++) {
#pragma unroll
        for (int kh = 0; kh < 3; kh++) {
            const float4 va = *(const float4*)&tile[ic][r + kh][4 * g];
            const float2 vb = *(const float2*)&tile[ic][r + kh][4 * g + 4];
            float t[6] = {va.x, va.y, va.z, va.w, vb.x, vb.y};
#pragma unroll
            for (int kw = 0; kw < 3; kw++) {
                float4 wv = wq[ic * 9 + kh * 3 + kw];
#pragma unroll
                for (int p = 0; p < 4; p++) {
                    float u = t[p + kw];
                    y[0][p] = fmaf(wv.x, u, y[0][p]);
                    y[1][p] = fmaf(wv.y, u, y[1][p]);
                    y[2][p] = fmaf(wv.z, u, y[2][p]);
                    y[3][p] = fmaf(wv.w, u, y[3][p]);
                }
            }
        }
    }

    // bn2 stats on true y (sum re-signed; sumsq sign-invariant)
#pragma unroll
    for (int j = 0; j < 4; j++) {
        float s = (y[j][0] + y[j][1]) + (y[j][2] + y[j][3]);
        float qq = fmaf(y[j][0], y[j][0], fmaf(y[j][1], y[j][1],
                   fmaf(y[j][2], y[j][2], y[j][3] * y[j][3])));
        float ws = warp_sum(s);
        float wq = warp_sum(qq);
        if ((tid & 31) == 0) {
            atomicAdd(&sacc[j], (double)(ws * s_s2[j]));
            atomicAdd(&sacc[4 + j], (double)wq);
        }
    }

    // stash y' into ybuf for in-block 2x2 max pooling
#pragma unroll
    for (int p = 0; p < 4; p++)
        ybuf[r][4 * g + p] = make_float4(y[0][p], y[1][p], y[2][p], y[3][p]);
    __syncthreads();

    // 224 threads = 4 pooled rows x 56 pooled cols, single plane out
    {
        const int ppr = tid / 56, ppw = tid % 56;
        float4 u0 = ybuf[2 * ppr][2 * ppw];
        float4 u1 = ybuf[2 * ppr][2 * ppw + 1];
        float4 u2 = ybuf[2 * ppr + 1][2 * ppw];
        float4 u3 = ybuf[2 * ppr + 1][2 * ppw + 1];
        float4 mx;
        mx.x = fmaxf(fmaxf(u0.x, u1.x), fmaxf(u2.x, u3.x));
        mx.y = fmaxf(fmaxf(u0.y, u1.y), fmaxf(u2.y, u3.y));
        mx.z = fmaxf(fmaxf(u0.z, u1.z), fmaxf(u2.z, u3.z));
        mx.w = fmaxf(fmaxf(u0.w, u1.w), fmaxf(u2.w, u3.w));
        size_t o = (((size_t)n * 56 + (blockIdx.x * 4 + ppr)) * 56 + ppw) * 4;
        *(float4*)&g_p2[o] = mx;
    }
    if (tid < 8) atomicAdd(&g_stats2[tid], sacc[tid]);
}

// ---------------------------------------------------------------------------
// Quantum circuit helpers.
template <int Q>
__device__ __forceinline__ void ry_gate(float2* st, float t) {
    float s, c;
    sincosf(0.5f * t, &s, &c);
    const int m = 8 >> Q;
#pragma unroll
    for (int i = 0; i < 16; i++)
        if (!(i & m)) {
            float2 a0 = st[i], a1 = st[i | m];
            st[i]     = make_float2(c * a0.x - s * a1.x, c * a0.y - s * a1.y);
            st[i | m] = make_float2(s * a0.x + c * a1.x, s * a0.y + c * a1.y);
        }
}
template <int Q>
__device__ __forceinline__ void rz_gate(float2* st, float t) {
    float s, c;
    sincosf(0.5f * t, &s, &c);
    const int m = 8 >> Q;
#pragma unroll
    for (int i = 0; i < 16; i++)
        if (!(i & m)) {
            float2 a0 = st[i], a1 = st[i | m];
            st[i]     = make_float2(c * a0.x + s * a0.y, c * a0.y - s * a0.x);
            st[i | m] = make_float2(c * a1.x - s * a1.y, c * a1.y + s * a1.x);
        }
}
template <int Q>
__device__ __forceinline__ void rx_gate(float2* st, float t) {
    float s, c;
    sincosf(0.5f * t, &s, &c);
    const int m = 8 >> Q;
#pragma unroll
    for (int i = 0; i < 16; i++)
        if (!(i & m)) {
            float2 a0 = st[i], a1 = st[i | m];
            st[i]     = make_float2(c * a0.x + s * a1.y, c * a0.y - s * a1.x);
            st[i | m] = make_float2(c * a1.x + s * a0.y, c * a1.y - s * a0.x);
        }
}
template <int C, int T>
__device__ __forceinline__ void cnot_gate(float2* st) {
    const int mc = 8 >> C, mt = 8 >> T;
#pragma unroll
    for (int i = 0; i < 16; i++)
        if ((i & mc) && !(i & mt)) {
            float2 tmp = st[i];
            st[i] = st[i | mt];
            st[i | mt] = tmp;
        }
}

// ---------------------------------------------------------------------------
// pool_mean + fused final.  grid(128), block 256.
__global__ void k_pool_final(const float* __restrict__ bn2g,
                             const float* __restrict__ bn2b,
                             const float* __restrict__ theta,
                             const float* __restrict__ rho,
                             const float* __restrict__ ng,
                             const float* __restrict__ nb,
                             float* __restrict__ out) {
    __shared__ float s_a2[4], s_c2[4];
    __shared__ unsigned int s_last;
    const int n = blockIdx.x, tid = threadIdx.x;
    if (tid < 4) {
        double N = 128.0 * 112.0 * 112.0;
        double mu = g_stats2[tid] / N;
        double var = g_stats2[4 + tid] / N - mu * mu;
        double a = (double)bn2g[tid] * rsqrt(var + 1e-5);
        s_a2[tid] = fabsf((float)a);
        s_c2[tid] = (float)((double)bn2b[tid] - mu * a);
    }
    __syncthreads();
    const float4 av = *(const float4*)s_a2;
    const float4 cv = *(const float4*)s_c2;
    const float4* psel = (const float4*)&g_p2[(size_t)n * 56 * 56 * 4];
    float4 acc = make_float4(0.f, 0.f, 0.f, 0.f);

    for (int p = tid; p < 56 * 56; p += 256) {
        float4 mx = psel[p];
        acc.x += fmaxf(fmaf(mx.x, av.x, cv.x), 0.f);
        acc.y += fmaxf(fmaf(mx.y, av.y, cv.y), 0.f);
        acc.z += fmaxf(fmaf(mx.z, av.z, cv.z), 0.f);
        acc.w += fmaxf(fmaf(mx.w, av.w, cv.w), 0.f);
    }
    __shared__ float4 sm[8];
    acc.x = warp_sum(acc.x); acc.y = warp_sum(acc.y);
    acc.z = warp_sum(acc.z); acc.w = warp_sum(acc.w);
    if ((tid & 31) == 0) sm[tid >> 5] = acc;
    __syncthreads();
    if (tid == 0) {
        float4 t = make_float4(0.f, 0.f, 0.f, 0.f);
#pragma unroll
        for (int i = 0; i < 8; i++) {
            t.x += sm[i].x; t.y += sm[i].y; t.z += sm[i].z; t.w += sm[i].w;
        }
        *(float4*)&g_feat[n * 4] =
            make_float4(t.x / 3136.f, t.y / 3136.f, t.z / 3136.f, t.w / 3136.f);
        __threadfence();
        s_last = atomicAdd(&g_done, 1u);
    }
    __syncthreads();
    if (s_last != NB - 1) return;
    __threadfence();

    if (tid == 0) g_done = 0;
    if (tid < 8)  g_q1[tid] = 0.0;
    if (tid < 9)  g_xs[tid] = 0.0;
    if (tid < 8)  g_stats2[tid] = 0.0;
    if (tid >= 128) return;

    float f[4];
#pragma unroll
    for (int j = 0; j < 4; j++) f[j] = g_feat[tid * 4 + j];

    __shared__ double ssum, ssq;
    if (tid == 0) { ssum = 0.0; ssq = 0.0; }
    __syncthreads();
    float lf = f[0] + f[1] + f[2] + f[3];
    float lq = f[0] * f[0] + f[1] * f[1] + f[2] * f[2] + f[3] * f[3];
    float ws = warp_sum(lf), wq = warp_sum(lq);
    if ((tid & 31) == 0) { atomicAdd(&ssum, (double)ws); atomicAdd(&ssq, (double)wq); }
    __syncthreads();
    double mean = ssum / 512.0;
    double var1 = (ssq - 512.0 * mean * mean) / 511.0;
    if (var1 < 0.0) var1 = 0.0;
    float scale = (float)(3.14159265358979323846 / (sqrt(var1) + 1e-6));
    float sc[4];
#pragma unroll
    for (int j = 0; j < 4; j++) sc[j] = (float)((double)f[j] - mean) * scale;

    float2 st[16];
#pragma unroll
    for (int i = 0; i < 16; i++) st[i] = make_float2(0.f, 0.f);
    st[0].x = 1.f;

    ry_gate<0>(st, sc[0]); ry_gate<1>(st, sc[1]); ry_gate<2>(st, sc[2]); ry_gate<3>(st, sc[3]);

    ry_gate<0>(st, theta[0]);  rz_gate<0>(st, theta[1]);  rx_gate<0>(st, theta[2]);
    ry_gate<1>(st, theta[3]);  rz_gate<1>(st, theta[4]);  rx_gate<1>(st, theta[5]);
    ry_gate<2>(st, theta[6]);  rz_gate<2>(st, theta[7]);  rx_gate<2>(st, theta[8]);
    ry_gate<3>(st, theta[9]);  rz_gate<3>(st, theta[10]); rx_gate<3>(st, theta[11]);

    cnot_gate<0, 1>(st); cnot_gate<1, 2>(st); cnot_gate<2, 3>(st);

    ry_gate<0>(st, rho[0]);  rz_gate<0>(st, rho[1]);  rx_gate<0>(st, rho[2]);
    ry_gate<1>(st, rho[3]);  rz_gate<1>(st, rho[4]);  rx_gate<1>(st, rho[5]);
    ry_gate<2>(st, rho[6]);  rz_gate<2>(st, rho[7]);  rx_gate<2>(st, rho[8]);
    ry_gate<3>(st, rho[9]);  rz_gate<3>(st, rho[10]); rx_gate<3>(st, rho[11]);

    cnot_gate<1, 0>(st); cnot_gate<2, 1>(st); cnot_gate<3, 2>(st);

    float pr[16];
#pragma unroll
    for (int i = 0; i < 16; i++) pr[i] = st[i].x * st[i].x + st[i].y * st[i].y;

    float e[4];
#pragma unroll
    for (int q = 0; q < 4; q++) {
        const int m = 8 >> q;
        float a = 0.f;
#pragma unroll
        for (int i = 0; i < 16; i++) a += (i & m) ? -pr[i] : pr[i];
        e[q] = a;
    }

    __shared__ double s1, s2;
#pragma unroll
    for (int j = 0; j < 4; j++) {
        if (tid == 0) { s1 = 0.0; s2 = 0.0; }
        __syncthreads();
        float v = e[j];
        float w1 = warp_sum(v), w2 = warp_sum(v * v);
        if ((tid & 31) == 0) { atomicAdd(&s1, (double)w1); atomicAdd(&s2, (double)w2); }
        __syncthreads();
        double mu = s1 / 128.0;
        double vv = s2 / 128.0 - mu * mu;
        out[tid * 4 + j] =
            (float)(((double)v - mu) * rsqrt(vv + 1e-5) * (double)ng[j] + (double)nb[j]);
        __syncthreads();
    }
}

// ---------------------------------------------------------------------------
extern "C" void kernel_launch(void* const* d_in, const int* in_sizes, int n_in,
                              void* d_out, int out_size) {
    const float* x     = (const float*)d_in[0];
    const float* w1    = (const float*)d_in[1];
    const float* b1    = (const float*)d_in[2];
    const float* bn1g  = (const float*)d_in[3];
    const float* bn1b  = (const float*)d_in[4];
    const float* w2    = (const float*)d_in[5];
    const float* b2    = (const float*)d_in[6];
    const float* bn2g  = (const float*)d_in[7];
    const float* bn2b  = (const float*)d_in[8];
    const float* theta = (const float*)d_in[9];
    const float* rho   = (const float*)d_in[10];
    const float* ng    = (const float*)d_in[11];
    const float* nbp   = (const float*)d_in[12];
    float* out = (float*)d_out;

    k_conv1<<<dim3(14, NB), 224>>>(x, w1, b1, bn1g);
    k_conv2<<<dim3(14, NB), 224>>>(w2, b2, w1, b1, bn1g, bn1b, bn2g);
    k_pool_final<<<NB, 256>>>(bn2g, bn2b, theta, rho, ng, nbp, out);
}

// round 16
// speedup vs baseline: 1.1743x; 1.0191x over previous
#include <cuda_runtime.h>
#include <math.h>

// ---------------------------------------------------------------------------
// QuantumNATExtendedQML — R15: analytic conv1 mean (R15 conv1, 41.5us) +
// bn1 affine computed ONCE in conv1's last-block tail (double math executed
// 1x/launch instead of 1792x in conv2 prologues). conv2 prologue = 8 float
// loads. Pipeline: conv1 -> conv2 -> pool_final (3 launches).
// ---------------------------------------------------------------------------

#define NB 128

// persistent device scratch (no cudaMalloc allowed); zero-initialized.
__device__ double g_q1[8];                                 // sumsq per conv1 channel
__device__ double g_xs[9];                                 // T, R0, R223, C0, C223, 4 corners
__device__ double g_stats2[8];                             // sum[4], sumsq[4] conv2 (true y)
__device__ unsigned int g_done1;                           // conv1 block counter
__device__ unsigned int g_done;                            // pool-block counter
__device__ __align__(16) float g_a1f[8], g_c1f[8];         // bn1 affine (|a|, c), computed once
__device__ __align__(16) float g_h1[NB * 112 * 112 * 8];   // pooled extremum of s1*z, ch-last
__device__ __align__(16) float g_p2[NB * 56 * 56 * 4];     // pooled extremum of s2*y, ch-last
__device__ __align__(16) float g_feat[NB * 4];

__device__ __forceinline__ float warp_sum(float v) {
#pragma unroll
    for (int o = 16; o > 0; o >>= 1) v += __shfl_xor_sync(0xffffffffu, v, o);
    return v;
}

// ---------------------------------------------------------------------------
// Fused conv1: z' = s*conv(x) -> per-channel sumsq atomics + image scalars
// (analytic mean) + 2x2 pooled max(z'); LAST block derives bn1 affine.
// grid(14, 128), block 224, 5 blocks/SM (regcap).
__global__ void __launch_bounds__(224, 5) k_conv1(const float* __restrict__ x,
                                                  const float* __restrict__ w,
                                                  const float* __restrict__ bias,
                                                  const float* __restrict__ bn1g,
                                                  const float* __restrict__ w1full,
                                                  const float* __restrict__ b1full,
                                                  const float* __restrict__ bn1b) {
    __shared__ __align__(16) float tile[18][228];
    __shared__ double sacc[9];    // [0..7] sumsq partials, [8] T partial
    __shared__ unsigned int s_old;
    const int n = blockIdx.y, h0 = blockIdx.x * 16, tid = threadIdx.x;
    const int grp = tid & 3, k = tid >> 2, lane = tid & 31;

    if (tid < 9) sacc[tid] = 0.0;

    // column-owner tile load; T accumulated unconditionally (halo = 0)
    const float* xim = x + (size_t)n * 224 * 224;
    float tloc = 0.f;
    for (int c = tid; c < 226; c += 224) {
        const int ww = c - 1;
        const bool cok = (ww >= 0) && (ww < 224);
#pragma unroll 2
        for (int r = 0; r < 18; r++) {
            int hh = h0 - 1 + r;
            float v = 0.f;
            if (cok && hh >= 0 && hh < 224) v = xim[hh * 224 + ww];
            tile[r][c] = v;
            if (r >= 1 && r <= 16) tloc += v;   // compile-time condition
        }
    }

    float wr[18], br[2];
#pragma unroll
    for (int j = 0; j < 2; j++) {
        int oc = grp * 2 + j;
        float s = (bn1g[oc] >= 0.f) ? 1.f : -1.f;
#pragma unroll
        for (int t = 0; t < 9; t++) wr[j * 9 + t] = w[oc * 9 + t] * s;
        br[j] = bias[oc] * s;
    }
    __syncthreads();

    // ---- scalar epilogue (once per block, outside hot loops) ----
    {
        float wt = warp_sum(tloc);
        if (lane == 0) atomicAdd(&sacc[8], (double)wt);
        if (blockIdx.x == 0) {       // rows with hh==0 live at tile r=1
            float r0 = tile[1][tid] + ((tid + 224 < 226) ? tile[1][tid + 224] : 0.f);
            float wr0 = warp_sum(r0);
            if (lane == 0) atomicAdd(&g_xs[1], (double)wr0);
        }
        if (blockIdx.x == 13) {      // rows with hh==223 live at tile r=16
            float r1 = tile[16][tid] + ((tid + 224 < 226) ? tile[16][tid + 224] : 0.f);
            float wr1 = warp_sum(r1);
            if (lane == 0) atomicAdd(&g_xs[2], (double)wr1);
        }
        if (tid == 0) {
            float c0 = 0.f, c1 = 0.f;
#pragma unroll
            for (int r = 1; r <= 16; r++) { c0 += tile[r][1]; c1 += tile[r][224]; }
            atomicAdd(&g_xs[3], (double)c0);
            atomicAdd(&g_xs[4], (double)c1);
            if (blockIdx.x == 0) {
                atomicAdd(&g_xs[5], (double)tile[1][1]);
                atomicAdd(&g_xs[6], (double)tile[1][224]);
            }
            if (blockIdx.x == 13) {
                atomicAdd(&g_xs[7], (double)tile[16][1]);
                atomicAdd(&g_xs[8], (double)tile[16][224]);
            }
        }
    }

    const int c0 = 4 * k;
    float w0[6], w1[6];
    {
        float4 a0 = *(const float4*)&tile[0][c0];
        float2 b0 = *(const float2*)&tile[0][c0 + 4];
        w0[0] = a0.x; w0[1] = a0.y; w0[2] = a0.z; w0[3] = a0.w; w0[4] = b0.x; w0[5] = b0.y;
        float4 a1 = *(const float4*)&tile[1][c0];
        float2 b1 = *(const float2*)&tile[1][c0 + 4];
        w1[0] = a1.x; w1[1] = a1.y; w1[2] = a1.z; w1[3] = a1.w; w1[4] = b1.x; w1[5] = b1.y;
    }

    float q[2] = {0.f, 0.f};
    float mx[2][2];
    float* psel = &g_h1[(((size_t)n * 112 + blockIdx.x * 8) * 112 + 2 * k) * 8 + 2 * grp];

#pragma unroll 4
    for (int r = 0; r < 16; r++) {
        float w2v[6];
        {
            float4 a = *(const float4*)&tile[r + 2][c0];
            float2 b = *(const float2*)&tile[r + 2][c0 + 4];
            w2v[0] = a.x; w2v[1] = a.y; w2v[2] = a.z; w2v[3] = a.w; w2v[4] = b.x; w2v[5] = b.y;
        }
#pragma unroll
        for (int j = 0; j < 2; j++) {
            float z[4];
#pragma unroll
            for (int p = 0; p < 4; p++) {
                float zz = br[j];
                zz = fmaf(wr[j * 9 + 0], w0[p + 0], zz);
                zz = fmaf(wr[j * 9 + 1], w0[p + 1], zz);
                zz = fmaf(wr[j * 9 + 2], w0[p + 2], zz);
                zz = fmaf(wr[j * 9 + 3], w1[p + 0], zz);
                zz = fmaf(wr[j * 9 + 4], w1[p + 1], zz);
                zz = fmaf(wr[j * 9 + 5], w1[p + 2], zz);
                zz = fmaf(wr[j * 9 + 6], w2v[p + 0], zz);
                zz = fmaf(wr[j * 9 + 7], w2v[p + 1], zz);
                zz = fmaf(wr[j * 9 + 8], w2v[p + 2], zz);
                z[p] = zz;
            }
            q[j] = fmaf(z[0], z[0], fmaf(z[1], z[1], fmaf(z[2], z[2], fmaf(z[3], z[3], q[j]))));
            float h0m = fmaxf(z[0], z[1]), h1m = fmaxf(z[2], z[3]);
            if (r & 1) {
                mx[j][0] = fmaxf(mx[j][0], h0m);
                mx[j][1] = fmaxf(mx[j][1], h1m);
            } else {
                mx[j][0] = h0m;
                mx[j][1] = h1m;
            }
        }
        if (r & 1) {
            *(float2*)psel       = make_float2(mx[0][0], mx[1][0]);
            *(float2*)(psel + 8) = make_float2(mx[0][1], mx[1][1]);
            psel += 112 * 8;
        }
#pragma unroll
        for (int i = 0; i < 6; i++) { w0[i] = w1[i]; w1[i] = w2v[i]; }
    }

    // same-group sumsq reduction (lanes 4 apart); sumsq is sign-invariant.
#pragma unroll
    for (int j = 0; j < 2; j++) {
        float qq = q[j];
#pragma unroll
        for (int o = 4; o < 32; o <<= 1) qq += __shfl_xor_sync(0xffffffffu, qq, o);
        if (lane < 4) atomicAdd(&sacc[lane * 2 + j], (double)qq);
    }
    __syncthreads();
    if (tid < 8) atomicAdd(&g_q1[tid], sacc[tid]);
    else if (tid == 8) atomicAdd(&g_xs[0], sacc[8]);

    // ---- last-block tail: derive bn1 affine once per launch ----
    __threadfence();
    __syncthreads();
    if (tid == 0) s_old = atomicAdd(&g_done1, 1u);
    __syncthreads();
    if (s_old != 14u * NB - 1u) return;
    __threadfence();   // acquire: all blocks' stats visible
    if (tid < 8) {
        const double N = 128.0 * 224.0 * 224.0;
        double T = g_xs[0], R0 = g_xs[1], R223 = g_xs[2], C0 = g_xs[3], C223 = g_xs[4];
        double x00 = g_xs[5], x0W = g_xs[6], xH0 = g_xs[7], xHW = g_xs[8];
        double Ssum = 0.0;
#pragma unroll
        for (int kh = 0; kh < 3; kh++)
#pragma unroll
            for (int kw = 0; kw < 3; kw++) {
                double S = T;
                if (kh == 2) S -= R0;
                if (kh == 0) S -= R223;
                if (kw == 2) S -= C0;
                if (kw == 0) S -= C223;
                if (kh == 2 && kw == 2) S += x00;
                if (kh == 2 && kw == 0) S += x0W;
                if (kh == 0 && kw == 2) S += xH0;
                if (kh == 0 && kw == 0) S += xHW;
                Ssum += (double)w1full[tid * 9 + kh * 3 + kw] * S;
            }
        double mu = Ssum / N + (double)b1full[tid];
        double var = g_q1[tid] / N - mu * mu;
        double a = (double)bn1g[tid] * rsqrt(var + 1e-5);
        g_a1f[tid] = fabsf((float)a);
        g_c1f[tid] = (float)((double)bn1b[tid] - mu * a);
    }
}

// ---------------------------------------------------------------------------
// conv2 (oc 0..3): prologue = 8 float loads of the precomputed bn1 affine.
// Tile load: h = relu(|a1|*stored + c1). s2 folded into w2,b2; stats
// re-signed to g_stats2; in-block 2x2 pooled max(y') out.
// grid(14, 128), block 224.
__global__ void __launch_bounds__(224) k_conv2(const float* __restrict__ w2,
                                               const float* __restrict__ b2,
                                               const float* __restrict__ bn2g) {
    __shared__ float tile[8][10][120];
    __shared__ float4 wq[72];
    __shared__ float4 ybuf[8][112];
    __shared__ float bsh[4], s_s2[4], s_a1[8], s_c1[8];
    __shared__ double sacc[8];
    const int n = blockIdx.y, h0 = blockIdx.x * 8, tid = threadIdx.x;

    if (tid < 8) {
        s_a1[tid] = g_a1f[tid];
        s_c1[tid] = g_c1f[tid];
    }
    if (tid < 72) {
        float sg0 = bn2g[0] >= 0.f ? 1.f : -1.f;
        float sg1 = bn2g[1] >= 0.f ? 1.f : -1.f;
        float sg2 = bn2g[2] >= 0.f ? 1.f : -1.f;
        float sg3 = bn2g[3] >= 0.f ? 1.f : -1.f;
        wq[tid] = make_float4(w2[tid] * sg0, w2[72 + tid] * sg1,
                              w2[144 + tid] * sg2, w2[216 + tid] * sg3);
    }
    if (tid < 4) {
        float sgn = bn2g[tid] >= 0.f ? 1.f : -1.f;
        s_s2[tid] = sgn;
        bsh[tid] = b2[tid] * sgn;
    }
    if (tid < 8) sacc[tid] = 0.0;
    __syncthreads();

    float a1r[8], c1r[8];
#pragma unroll
    for (int ch = 0; ch < 8; ch++) { a1r[ch] = s_a1[ch]; c1r[ch] = s_c1[ch]; }

    // column-owner tile load: thread owns tile col c (<114), loops 10 rows
    for (int c = tid; c < 114; c += 224) {
        const int ww = c - 1;
        const bool cok = (ww >= 0) && (ww < 112);
#pragma unroll 2
        for (int r = 0; r < 10; r++) {
            int hh = h0 - 1 + r;
            float v[8];
            if (cok && hh >= 0 && hh < 112) {
                size_t base = (((size_t)n * 112 + hh) * 112 + ww) * 8;
                float4 x0 = *(const float4*)&g_h1[base];
                float4 x1 = *(const float4*)&g_h1[base + 4];
                float raw[8] = {x0.x, x0.y, x0.z, x0.w, x1.x, x1.y, x1.z, x1.w};
#pragma unroll
                for (int ch = 0; ch < 8; ch++)
                    v[ch] = fmaxf(fmaf(raw[ch], a1r[ch], c1r[ch]), 0.f);
            } else {
#pragma unroll
                for (int ch = 0; ch < 8; ch++) v[ch] = 0.f;
            }
#pragma unroll
            for (int ch = 0; ch < 8; ch++) tile[ch][r][c] = v[ch];
        }
    }
    __syncthreads();

    const int r = tid / 28, g = tid % 28;
    float y[4][4];
    {
        float b0 = bsh[0], b1v = bsh[1], b2v = bsh[2], b3 = bsh[3];
#pragma unroll
        for (int p = 0; p < 4; p++) {
            y[0][p] = b0; y[1][p] = b1v; y[2][p] = b2v; y[3][p] = b3;
        }
    }

#pragma unroll 1
    for (int ic = 0; ic < 8; ic++) {
#pragma unroll
        for (int kh = 0; kh < 3; kh++) {
            const float4 va = *(const float4*)&tile[ic][r + kh][4 * g];
            const float2 vb = *(const float2*)&tile[ic][r + kh][4 * g + 4];
            float t[6] = {va.x, va.y, va.z, va.w, vb.x, vb.y};
#pragma unroll
            for (int kw = 0; kw < 3; kw++) {
                float4 wv = wq[ic * 9 + kh * 3 + kw];
#pragma unroll
                for (int p = 0; p < 4; p++) {
                    float u = t[p + kw];
                    y[0][p] = fmaf(wv.x, u, y[0][p]);
                    y[1][p] = fmaf(wv.y, u, y[1][p]);
                    y[2][p] = fmaf(wv.z, u, y[2][p]);
                    y[3][p] = fmaf(wv.w, u, y[3][p]);
                }
            }
        }
    }

    // bn2 stats on true y (sum re-signed; sumsq sign-invariant)
#pragma unroll
    for (int j = 0; j < 4; j++) {
        float s = (y[j][0] + y[j][1]) + (y[j][2] + y[j][3]);
        float qq = fmaf(y[j][0], y[j][0], fmaf(y[j][1], y[j][1],
                   fmaf(y[j][2], y[j][2], y[j][3] * y[j][3])));
        float ws = warp_sum(s);
        float wq = warp_sum(qq);
        if ((tid & 31) == 0) {
            atomicAdd(&sacc[j], (double)(ws * s_s2[j]));
            atomicAdd(&sacc[4 + j], (double)wq);
        }
    }

    // stash y' into ybuf for in-block 2x2 max pooling
#pragma unroll
    for (int p = 0; p < 4; p++)
        ybuf[r][4 * g + p] = make_float4(y[0][p], y[1][p], y[2][p], y[3][p]);
    __syncthreads();

    // 224 threads = 4 pooled rows x 56 pooled cols, single plane out
    {
        const int ppr = tid / 56, ppw = tid % 56;
        float4 u0 = ybuf[2 * ppr][2 * ppw];
        float4 u1 = ybuf[2 * ppr][2 * ppw + 1];
        float4 u2 = ybuf[2 * ppr + 1][2 * ppw];
        float4 u3 = ybuf[2 * ppr + 1][2 * ppw + 1];
        float4 mx;
        mx.x = fmaxf(fmaxf(u0.x, u1.x), fmaxf(u2.x, u3.x));
        mx.y = fmaxf(fmaxf(u0.y, u1.y), fmaxf(u2.y, u3.y));
        mx.z = fmaxf(fmaxf(u0.z, u1.z), fmaxf(u2.z, u3.z));
        mx.w = fmaxf(fmaxf(u0.w, u1.w), fmaxf(u2.w, u3.w));
        size_t o = (((size_t)n * 56 + (blockIdx.x * 4 + ppr)) * 56 + ppw) * 4;
        *(float4*)&g_p2[o] = mx;
    }
    if (tid < 8) atomicAdd(&g_stats2[tid], sacc[tid]);
}

// ---------------------------------------------------------------------------
// Quantum circuit helpers.
template <int Q>
__device__ __forceinline__ void ry_gate(float2* st, float t) {
    float s, c;
    sincosf(0.5f * t, &s, &c);
    const int m = 8 >> Q;
#pragma unroll
    for (int i = 0; i < 16; i++)
        if (!(i & m)) {
            float2 a0 = st[i], a1 = st[i | m];
            st[i]     = make_float2(c * a0.x - s * a1.x, c * a0.y - s * a1.y);
            st[i | m] = make_float2(s * a0.x + c * a1.x, s * a0.y + c * a1.y);
        }
}
template <int Q>
__device__ __forceinline__ void rz_gate(float2* st, float t) {
    float s, c;
    sincosf(0.5f * t, &s, &c);
    const int m = 8 >> Q;
#pragma unroll
    for (int i = 0; i < 16; i++)
        if (!(i & m)) {
            float2 a0 = st[i], a1 = st[i | m];
            st[i]     = make_float2(c * a0.x + s * a0.y, c * a0.y - s * a0.x);
            st[i | m] = make_float2(c * a1.x - s * a1.y, c * a1.y + s * a1.x);
        }
}
template <int Q>
__device__ __forceinline__ void rx_gate(float2* st, float t) {
    float s, c;
    sincosf(0.5f * t, &s, &c);
    const int m = 8 >> Q;
#pragma unroll
    for (int i = 0; i < 16; i++)
        if (!(i & m)) {
            float2 a0 = st[i], a1 = st[i | m];
            st[i]     = make_float2(c * a0.x + s * a1.y, c * a0.y - s * a1.x);
            st[i | m] = make_float2(c * a1.x + s * a0.y, c * a1.y - s * a0.x);
        }
}
template <int C, int T>
__device__ __forceinline__ void cnot_gate(float2* st) {
    const int mc = 8 >> C, mt = 8 >> T;
#pragma unroll
    for (int i = 0; i < 16; i++)
        if ((i & mc) && !(i & mt)) {
            float2 tmp = st[i];
            st[i] = st[i | mt];
            st[i | mt] = tmp;
        }
}

// ---------------------------------------------------------------------------
// pool_mean + fused final.  grid(128), block 256.
__global__ void k_pool_final(const float* __restrict__ bn2g,
                             const float* __restrict__ bn2b,
                             const float* __restrict__ theta,
                             const float* __restrict__ rho,
                             const float* __restrict__ ng,
                             const float* __restrict__ nb,
                             float* __restrict__ out) {
    __shared__ float s_a2[4], s_c2[4];
    __shared__ unsigned int s_last;
    const int n = blockIdx.x, tid = threadIdx.x;
    if (tid < 4) {
        double N = 128.0 * 112.0 * 112.0;
        double mu = g_stats2[tid] / N;
        double var = g_stats2[4 + tid] / N - mu * mu;
        double a = (double)bn2g[tid] * rsqrt(var + 1e-5);
        s_a2[tid] = fabsf((float)a);
        s_c2[tid] = (float)((double)bn2b[tid] - mu * a);
    }
    __syncthreads();
    const float4 av = *(const float4*)s_a2;
    const float4 cv = *(const float4*)s_c2;
    const float4* psel = (const float4*)&g_p2[(size_t)n * 56 * 56 * 4];
    float4 acc = make_float4(0.f, 0.f, 0.f, 0.f);

    for (int p = tid; p < 56 * 56; p += 256) {
        float4 mx = psel[p];
        acc.x += fmaxf(fmaf(mx.x, av.x, cv.x), 0.f);
        acc.y += fmaxf(fmaf(mx.y, av.y, cv.y), 0.f);
        acc.z += fmaxf(fmaf(mx.z, av.z, cv.z), 0.f);
        acc.w += fmaxf(fmaf(mx.w, av.w, cv.w), 0.f);
    }
    __shared__ float4 sm[8];
    acc.x = warp_sum(acc.x); acc.y = warp_sum(acc.y);
    acc.z = warp_sum(acc.z); acc.w = warp_sum(acc.w);
    if ((tid & 31) == 0) sm[tid >> 5] = acc;
    __syncthreads();
    if (tid == 0) {
        float4 t = make_float4(0.f, 0.f, 0.f, 0.f);
#pragma unroll
        for (int i = 0; i < 8; i++) {
            t.x += sm[i].x; t.y += sm[i].y; t.z += sm[i].z; t.w += sm[i].w;
        }
        *(float4*)&g_feat[n * 4] =
            make_float4(t.x / 3136.f, t.y / 3136.f, t.z / 3136.f, t.w / 3136.f);
        __threadfence();
        s_last = atomicAdd(&g_done, 1u);
    }
    __syncthreads();
    if (s_last != NB - 1) return;
    __threadfence();

    if (tid == 0) { g_done = 0; g_done1 = 0; }
    if (tid < 8)  g_q1[tid] = 0.0;
    if (tid < 9)  g_xs[tid] = 0.0;
    if (tid < 8)  g_stats2[tid] = 0.0;
    if (tid >= 128) return;

    float f[4];
#pragma unroll
    for (int j = 0; j < 4; j++) f[j] = g_feat[tid * 4 + j];

    __shared__ double ssum, ssq;
    if (tid == 0) { ssum = 0.0; ssq = 0.0; }
    __syncthreads();
    float lf = f[0] + f[1] + f[2] + f[3];
    float lq = f[0] * f[0] + f[1] * f[1] + f[2] * f[2] + f[3] * f[3];
    float ws = warp_sum(lf), wq = warp_sum(lq);
    if ((tid & 31) == 0) { atomicAdd(&ssum, (double)ws); atomicAdd(&ssq, (double)wq); }
    __syncthreads();
    double mean = ssum / 512.0;
    double var1 = (ssq - 512.0 * mean * mean) / 511.0;
    if (var1 < 0.0) var1 = 0.0;
    float scale = (float)(3.14159265358979323846 / (sqrt(var1) + 1e-6));
    float sc[4];
#pragma unroll
    for (int j = 0; j < 4; j++) sc[j] = (float)((double)f[j] - mean) * scale;

    float2 st[16];
#pragma unroll
    for (int i = 0; i < 16; i++) st[i] = make_float2(0.f, 0.f);
    st[0].x = 1.f;

    ry_gate<0>(st, sc[0]); ry_gate<1>(st, sc[1]); ry_gate<2>(st, sc[2]); ry_gate<3>(st, sc[3]);

    ry_gate<0>(st, theta[0]);  rz_gate<0>(st, theta[1]);  rx_gate<0>(st, theta[2]);
    ry_gate<1>(st, theta[3]);  rz_gate<1>(st, theta[4]);  rx_gate<1>(st, theta[5]);
    ry_gate<2>(st, theta[6]);  rz_gate<2>(st, theta[7]);  rx_gate<2>(st, theta[8]);
    ry_gate<3>(st, theta[9]);  rz_gate<3>(st, theta[10]); rx_gate<3>(st, theta[11]);

    cnot_gate<0, 1>(st); cnot_gate<1, 2>(st); cnot_gate<2, 3>(st);

    ry_gate<0>(st, rho[0]);  rz_gate<0>(st, rho[1]);  rx_gate<0>(st, rho[2]);
    ry_gate<1>(st, rho[3]);  rz_gate<1>(st, rho[4]);  rx_gate<1>(st, rho[5]);
    ry_gate<2>(st, rho[6]);  rz_gate<2>(st, rho[7]);  rx_gate<2>(st, rho[8]);
    ry_gate<3>(st, rho[9]);  rz_gate<3>(st, rho[10]); rx_gate<3>(st, rho[11]);

    cnot_gate<1, 0>(st); cnot_gate<2, 1>(st); cnot_gate<3, 2>(st);

    float pr[16];
#pragma unroll
    for (int i = 0; i < 16; i++) pr[i] = st[i].x * st[i].x + st[i].y * st[i].y;

    float e[4];
#pragma unroll
    for (int q = 0; q < 4; q++) {
        const int m = 8 >> q;
        float a = 0.f;
#pragma unroll
        for (int i = 0; i < 16; i++) a += (i & m) ? -pr[i] : pr[i];
        e[q] = a;
    }

    __shared__ double s1, s2;
#pragma unroll
    for (int j = 0; j < 4; j++) {
        if (tid == 0) { s1 = 0.0; s2 = 0.0; }
        __syncthreads();
        float v = e[j];
        float w1 = warp_sum(v), w2 = warp_sum(v * v);
        if ((tid & 31) == 0) { atomicAdd(&s1, (double)w1); atomicAdd(&s2, (double)w2); }
        __syncthreads();
        double mu = s1 / 128.0;
        double vv = s2 / 128.0 - mu * mu;
        out[tid * 4 + j] =
            (float)(((double)v - mu) * rsqrt(vv + 1e-5) * (double)ng[j] + (double)nb[j]);
        __syncthreads();
    }
}

// ---------------------------------------------------------------------------
extern "C" void kernel_launch(void* const* d_in, const int* in_sizes, int n_in,
                              void* d_out, int out_size) {
    const float* x     = (const float*)d_in[0];
    const float* w1    = (const float*)d_in[1];
    const float* b1    = (const float*)d_in[2];
    const float* bn1g  = (const float*)d_in[3];
    const float* bn1b  = (const float*)d_in[4];
    const float* w2    = (const float*)d_in[5];
    const float* b2    = (const float*)d_in[6];
    const float* bn2g  = (const float*)d_in[7];
    const float* bn2b  = (const float*)d_in[8];
    const float* theta = (const float*)d_in[9];
    const float* rho   = (const float*)d_in[10];
    const float* ng    = (const float*)d_in[11];
    const float* nbp   = (const float*)d_in[12];
    float* out = (float*)d_out;

    k_conv1<<<dim3(14, NB), 224>>>(x, w1, b1, bn1g, w1, b1, bn1b);
    k_conv2<<<dim3(14, NB), 224>>>(w2, b2, bn2g);
    k_pool_final<<<NB, 256>>>(bn2g, bn2b, theta, rho, ng, nbp, out);
}